// round 14
// baseline (speedup 1.0000x reference)
#include <cuda_runtime.h>
#include <cuda_fp16.h>
#include <cstdint>

// ---------------------------------------------------------------------------
// QGroupLinear: y = x @ (qw*sw)^T + bias   (fp32 in/out)
// mma.sync (HMMA) GEMM, fp16 dequant scratch (rel_err ~3e-4).
// R14: warp-specialized concurrent prep. R11 mainloop (best known) + a 9th
// warp per CTA that converts X then dequantizes W into the tiled/swizzled
// scratch, publishing per-tile readiness counters. GEMM producer acquire-
// spins on readiness; prep overlaps the GEMM instead of running serially.
// ---------------------------------------------------------------------------

#define M_TOTAL 4096
#define N_TOTAL 11008
#define K_TOTAL 4096

#define BM 128
#define BN 256
#define STAGES 4
#define KT (K_TOTAL / 64)           // 64 chunks of 64 halfs
#define TILES_M (M_TOTAL / BM)      // 32
#define TILES_N (N_TOTAL / BN)      // 43
#define NTILES (TILES_M * TILES_N)  // 1376
#define NFULL 1368                  // 152 * 9
#define NUNITS (NFULL + (NTILES - NFULL) * 4)   // 1400
#define GRID 152

#define A_BLK_BYTES (BM * 128)      // 16384
#define B_BLK_BYTES (BN * 128)      // 32768
#define STAGE_BYTES (A_BLK_BYTES + B_BLK_BYTES)   // 49152

#define SM_FULL(s)  ((s) * 8)
#define SM_EMPTY(s) (32 + (s) * 8)
#define SM_TILEQ    64
#define SM_DATA     1024
#define SMEM_TOTAL  (SM_DATA + STAGES * STAGE_BYTES)   // 197632

__device__ uint4 d_X16T[2097152];   // 32 MB : block (m_tile*64+kc) = 16 KB
__device__ uint4 d_W16T[5636096];   // 90 MB : block (n_tile*64+kc) = 32 KB
__device__ int   g_tile_ctr;
__device__ int   g_x_cnt[TILES_M];  // rows converted per m_tile (target 128)
__device__ int   g_w_cnt[TILES_N];  // rows converted per n_tile (target 256)

// ---------------------------------------------------------------------------
__device__ __forceinline__ uint32_t smem_u32(const void* p) {
    uint32_t a;
    asm("{ .reg .u64 t; cvta.to.shared.u64 t, %1; cvt.u32.u64 %0, t; }"
        : "=r"(a) : "l"(p));
    return a;
}

__device__ __forceinline__ int ld_acquire(const int* p) {
    int v;
    asm volatile("ld.acquire.gpu.global.b32 %0, [%1];"
                 : "=r"(v) : "l"(__cvta_generic_to_global(p)) : "memory");
    return v;
}

#define MBARRIER_INIT(addr, cnt) \
    asm volatile("mbarrier.init.shared.b64 [%0], %1;" :: "r"((uint32_t)(addr)), "r"((uint32_t)(cnt)) : "memory")
#define MBARRIER_EXPECT_TX(addr, bytes) \
    asm volatile("mbarrier.arrive.expect_tx.shared.b64 _, [%0], %1;" :: "r"((uint32_t)(addr)), "r"((uint32_t)(bytes)) : "memory")
#define MBARRIER_ARRIVE(addr) \
    asm volatile("mbarrier.arrive.shared.b64 _, [%0];" :: "r"((uint32_t)(addr)) : "memory")
#define FENCE_PROXY_ASYNC() asm volatile("fence.proxy.async.shared::cta;" ::: "memory")

#define MBARRIER_WAIT_PARITY(mbar_smem_addr, phase_parity) do { \
    uint32_t _mbar = (uint32_t)(mbar_smem_addr); \
    uint32_t _parity = (uint32_t)(phase_parity); \
    uint32_t _done; \
    asm volatile( \
        "{\n\t.reg .pred p;\n\t" \
        "mbarrier.try_wait.parity.acquire.cta.shared::cta.b64 p, [%1], %2;\n\t" \
        "selp.b32 %0, 1, 0, p;\n\t}" \
        : "=r"(_done) : "r"(_mbar), "r"(_parity) : "memory"); \
    if (!_done) { \
        asm volatile( \
            "{\n\t.reg .pred P1;\n\t" \
            "WAIT_LOOP_%=:\n\t" \
            "mbarrier.try_wait.parity.acquire.cta.shared::cta.b64 P1, [%0], %1, 0x989680;\n\t" \
            "@P1 bra.uni WAIT_DONE_%=;\n\t" \
            "bra.uni WAIT_LOOP_%=;\n\t" \
            "WAIT_DONE_%=:\n\t}" \
            :: "r"(_mbar), "r"(_parity) : "memory"); \
    } \
} while (0)

#define BULK_G2S(dst, src, bytes, mbar) \
    asm volatile("cp.async.bulk.shared::cta.global.mbarrier::complete_tx::bytes [%0], [%1], %2, [%3];" \
        :: "r"((uint32_t)(dst)), "l"((unsigned long long)(src)), "r"((uint32_t)(bytes)), "r"((uint32_t)(mbar)) : "memory")

__device__ __forceinline__ void ldsm4(uint32_t* r, uint32_t addr) {
    asm volatile("ldmatrix.sync.aligned.m8n8.x4.shared.b16 {%0,%1,%2,%3}, [%4];"
                 : "=r"(r[0]), "=r"(r[1]), "=r"(r[2]), "=r"(r[3]) : "r"(addr));
}

__device__ __forceinline__ void mma16816(float* c, const uint32_t* a,
                                         uint32_t b0, uint32_t b1) {
    asm volatile(
        "mma.sync.aligned.m16n8k16.row.col.f32.f16.f16.f32 "
        "{%0,%1,%2,%3}, {%4,%5,%6,%7}, {%8,%9}, {%0,%1,%2,%3};"
        : "+f"(c[0]), "+f"(c[1]), "+f"(c[2]), "+f"(c[3])
        : "r"(a[0]), "r"(a[1]), "r"(a[2]), "r"(a[3]), "r"(b0), "r"(b1));
}

// unit decode: u < NFULL -> full tile; else quarter slice of tiles 1368..1375
__device__ __forceinline__ void decode_unit(int u, int& mt, int& nt, int& nlo) {
    if (u < NFULL) {
        mt = u & (TILES_M - 1); nt = u >> 5; nlo = 0;
    } else {
        int v = u - NFULL;
        int t = NFULL + (v >> 2);
        mt = t & (TILES_M - 1); nt = t >> 5; nlo = (v & 3) * 64;
    }
}

// spin until the prep warps have published this unit's tiles (tid0 only)
__device__ __forceinline__ void wait_unit_ready(int u) {
    int mt, nt, nlo;
    decode_unit(u, mt, nt, nlo);
    while (ld_acquire(&g_x_cnt[mt]) < BM) {}
    while (ld_acquire(&g_w_cnt[nt]) < BN) {}
}

__device__ __forceinline__ void fill_chunk(uint32_t sb, int cloc,
                                           const char* aG, const char* bG,
                                           uint32_t bbytes,
                                           int& estage, int& ephase) {
    MBARRIER_WAIT_PARITY(sb + SM_EMPTY(estage), ephase);
    if (++estage == STAGES) { estage = 0; ephase ^= 1; }
    int slot = cloc & 3;
    MBARRIER_EXPECT_TX(sb + SM_FULL(slot), A_BLK_BYTES + bbytes);
    BULK_G2S(sb + SM_DATA + slot * STAGE_BYTES,
             __cvta_generic_to_global(aG + ((size_t)cloc << 14)),
             A_BLK_BYTES, sb + SM_FULL(slot));
    BULK_G2S(sb + SM_DATA + slot * STAGE_BYTES + A_BLK_BYTES,
             __cvta_generic_to_global(bG + ((size_t)cloc << 15)),
             bbytes, sb + SM_FULL(slot));
}

// ---------------------------------------------------------------------------
// init kernel: reset scheduler + readiness counters (graph-replay-safe).
// ---------------------------------------------------------------------------
__global__ void init_kernel() {
    g_tile_ctr = 0;
    for (int i = 0; i < TILES_M; i++) g_x_cnt[i] = 0;
    for (int i = 0; i < TILES_N; i++) g_w_cnt[i] = 0;
}

// ---------------------------------------------------------------------------
// Prep (warp 8 of each CTA): convert X rows then W rows into the tiled +
// SW128-swizzled fp16 scratch; publish per-tile row counters (release).
// Per lane: 4 chunks of 16 values -> 16 independent 16B loads (MLP 16).
// ---------------------------------------------------------------------------
__device__ void prep_warp(int cta, int lane,
                          const float* __restrict__ x,
                          const int* __restrict__ qw,
                          const float* __restrict__ sw) {
    // ---- X rows ----
    for (int row = cta; row < M_TOTAL; row += GRID) {
        const float* xr = x + (size_t)row * K_TOTAL;
        char* base = (char*)d_X16T + (((size_t)(row >> 7) * KT) << 14);
        int rowl = row & 127;
        uint32_t rb = (uint32_t)rowl * 128;
        uint32_t sw_ = ((uint32_t)(rowl & 7)) << 4;
        #pragma unroll
        for (int it = 0; it < 2; it++) {
            int col0 = it * 2048 + lane * 16;
            float4 v[16];
            #pragma unroll
            for (int c = 0; c < 4; c++)
                #pragma unroll
                for (int j = 0; j < 4; j++)
                    v[c * 4 + j] = *(const float4*)(xr + col0 + c * 512 + j * 4);
            #pragma unroll
            for (int c = 0; c < 4; c++) {
                int k0 = col0 + c * 512;
                uint4 p0, p1;
                __half2 h;
                h = __floats2half2_rn(v[c*4+0].x, v[c*4+0].y); p0.x = *(uint32_t*)&h;
                h = __floats2half2_rn(v[c*4+0].z, v[c*4+0].w); p0.y = *(uint32_t*)&h;
                h = __floats2half2_rn(v[c*4+1].x, v[c*4+1].y); p0.z = *(uint32_t*)&h;
                h = __floats2half2_rn(v[c*4+1].z, v[c*4+1].w); p0.w = *(uint32_t*)&h;
                h = __floats2half2_rn(v[c*4+2].x, v[c*4+2].y); p1.x = *(uint32_t*)&h;
                h = __floats2half2_rn(v[c*4+2].z, v[c*4+2].w); p1.y = *(uint32_t*)&h;
                h = __floats2half2_rn(v[c*4+3].x, v[c*4+3].y); p1.z = *(uint32_t*)&h;
                h = __floats2half2_rn(v[c*4+3].z, v[c*4+3].w); p1.w = *(uint32_t*)&h;
                char* blkp = base + (((size_t)(k0 >> 6)) << 14) + rb;
                uint32_t ch = (uint32_t)(k0 & 63);
                *(uint4*)(blkp + ((ch * 2) ^ sw_)) = p0;
                *(uint4*)(blkp + (((ch + 8) * 2) ^ sw_)) = p1;
            }
        }
        __threadfence();
        if (lane == 0) atomicAdd(&g_x_cnt[row >> 7], 1);
    }
    // ---- W rows ----
    for (int row = cta; row < N_TOTAL; row += GRID) {
        const int* qr = qw + (size_t)row * K_TOTAL;
        const float* sr = sw + row * 32;
        char* base = (char*)d_W16T + (((size_t)(row >> 8) * KT) << 15);
        int rowl = row & 255;
        uint32_t rb = (uint32_t)rowl * 128;
        uint32_t sw_ = ((uint32_t)(rowl & 7)) << 4;
        #pragma unroll
        for (int it = 0; it < 2; it++) {
            int col0 = it * 2048 + lane * 16;
            int4 q[16];
            #pragma unroll
            for (int c = 0; c < 4; c++)
                #pragma unroll
                for (int j = 0; j < 4; j++)
                    q[c * 4 + j] = *(const int4*)(qr + col0 + c * 512 + j * 4);
            #pragma unroll
            for (int c = 0; c < 4; c++) {
                int k0 = col0 + c * 512;
                float s = sr[k0 >> 7];
                uint4 p0, p1;
                __half2 h;
                h = __floats2half2_rn((float)q[c*4+0].x * s, (float)q[c*4+0].y * s); p0.x = *(uint32_t*)&h;
                h = __floats2half2_rn((float)q[c*4+0].z * s, (float)q[c*4+0].w * s); p0.y = *(uint32_t*)&h;
                h = __floats2half2_rn((float)q[c*4+1].x * s, (float)q[c*4+1].y * s); p0.z = *(uint32_t*)&h;
                h = __floats2half2_rn((float)q[c*4+1].z * s, (float)q[c*4+1].w * s); p0.w = *(uint32_t*)&h;
                h = __floats2half2_rn((float)q[c*4+2].x * s, (float)q[c*4+2].y * s); p1.x = *(uint32_t*)&h;
                h = __floats2half2_rn((float)q[c*4+2].z * s, (float)q[c*4+2].w * s); p1.y = *(uint32_t*)&h;
                h = __floats2half2_rn((float)q[c*4+3].x * s, (float)q[c*4+3].y * s); p1.z = *(uint32_t*)&h;
                h = __floats2half2_rn((float)q[c*4+3].z * s, (float)q[c*4+3].w * s); p1.w = *(uint32_t*)&h;
                char* blkp = base + (((size_t)(k0 >> 6)) << 15) + rb;
                uint32_t ch = (uint32_t)(k0 & 63);
                *(uint4*)(blkp + ((ch * 2) ^ sw_)) = p0;
                *(uint4*)(blkp + (((ch + 8) * 2) ^ sw_)) = p1;
            }
        }
        __threadfence();
        if (lane == 0) atomicAdd(&g_w_cnt[row >> 8], 1);
    }
}

// ---------------------------------------------------------------------------
// Templated per-unit mainloop (R11). NJ = 8 (128x256) or 2 (128x64 quarter).
// ---------------------------------------------------------------------------
template <int NJ>
__device__ __forceinline__ void run_unit(uint32_t sb, int tid, int lane, int wid,
                                         int cur_unit, int ti, int* tileq,
                                         int& estage, int& ephase,
                                         int& fstage, int& fphase,
                                         const float* __restrict__ bias,
                                         float* __restrict__ out) {
    int warp_m = wid & 1;
    int warp_n = wid >> 1;
    int m_off = warp_m * 64;
    int n_off = warp_n * (NJ * 8);

    int m_tile, n_tile, n_lo;
    decode_unit(cur_unit, m_tile, n_tile, n_lo);

    const char* aG = (const char*)d_X16T + (((size_t)m_tile * KT) << 14);
    const char* bG = (const char*)d_W16T + (((size_t)n_tile * KT) << 15) + (size_t)n_lo * 128;
    const uint32_t bbytes = NJ * 4096;

    int rowA = m_off + (lane & 15);
    uint32_t xorA = (uint32_t)(rowA & 7) << 4;
    uint32_t cbA = ((uint32_t)(lane >> 4)) << 4;
    uint32_t aRow = sb + SM_DATA + (uint32_t)rowA * 128;

    int rowB = n_off + ((lane & 7) | ((lane & 16) >> 1));
    uint32_t xorB = (uint32_t)(rowB & 7) << 4;
    uint32_t cbB = ((uint32_t)((lane >> 3) & 1)) << 4;
    uint32_t bRow = sb + SM_DATA + A_BLK_BYTES + (uint32_t)rowB * 128;

    float acc[4][NJ][4];
    #pragma unroll
    for (int mi = 0; mi < 4; mi++)
        #pragma unroll
        for (int nj = 0; nj < NJ; nj++)
            #pragma unroll
            for (int r = 0; r < 4; r++) acc[mi][nj][r] = 0.0f;

    uint32_t fa[2][4][4], fb[2][NJ / 2][4];

    auto prefetch = [&](int buf, int s, int kk) {
        uint32_t ka = ((uint32_t)kk * 32 + cbA) ^ xorA;
        uint32_t kb = ((uint32_t)kk * 32 + cbB) ^ xorB;
        uint32_t aS = aRow + (uint32_t)s * STAGE_BYTES + ka;
        uint32_t bS = bRow + (uint32_t)s * STAGE_BYTES + kb;
        #pragma unroll
        for (int mi = 0; mi < 4; mi++)
            ldsm4(fa[buf][mi], aS + mi * (16 * 128));
        #pragma unroll
        for (int nj2 = 0; nj2 < NJ / 2; nj2++)
            ldsm4(fb[buf][nj2], bS + nj2 * (16 * 128));
    };

    int next_unit = -1;   // tid0 only

    // unit entry: wait chunks 0,1 and prime fragments
    MBARRIER_WAIT_PARITY(sb + SM_FULL(fstage), fphase);
    if (++fstage == STAGES) { fstage = 0; fphase ^= 1; }
    MBARRIER_WAIT_PARITY(sb + SM_FULL(fstage), fphase);
    if (++fstage == STAGES) { fstage = 0; fphase ^= 1; }
    prefetch(0, 0, 0);

    for (int kt = 0; kt < KT; kt++) {
        // ---- producer (tid0): fill chunk kt+3 (may spill into next unit) ----
        if (tid == 0) {
            if (kt == 0) {
                int t = atomicAdd(&g_tile_ctr, 1);
                next_unit = (t < NUNITS) ? t : -1;
                tileq[(ti + 1) & 3] = next_unit;
            }
            int lt = kt + STAGES - 1;
            if (lt < KT) {
                fill_chunk(sb, lt, aG, bG, bbytes, estage, ephase);
            } else if (next_unit >= 0) {
                if (lt == KT) wait_unit_ready(next_unit);   // first next-unit fill
                int nm, nn, nl;
                decode_unit(next_unit, nm, nn, nl);
                const char* pa = (const char*)d_X16T + (((size_t)nm * KT) << 14);
                const char* pb = (const char*)d_W16T + (((size_t)nn * KT) << 15) + (size_t)nl * 128;
                uint32_t nb = (next_unit < NFULL) ? 32768u : 8192u;
                fill_chunk(sb, lt - KT, pa, pb, nb, estage, ephase);
            }
        }

        int s = kt & (STAGES - 1);
        #pragma unroll
        for (int kk = 0; kk < 4; kk++) {
            int curb = kk & 1, nxt = curb ^ 1;
            if (kk < 3)
                prefetch(nxt, s, kk + 1);
            else if (kt + 1 < KT)
                prefetch(nxt, (kt + 1) & (STAGES - 1), 0);
            if (kk == 2 && lane == 0) MBARRIER_ARRIVE(sb + SM_EMPTY(s));
            #pragma unroll
            for (int mi = 0; mi < 4; mi++)
                #pragma unroll
                for (int nj = 0; nj < NJ; nj++)
                    mma16816(acc[mi][nj], fa[curb][mi],
                             fb[curb][nj >> 1][(nj & 1) * 2],
                             fb[curb][nj >> 1][(nj & 1) * 2 + 1]);
        }

        if (kt + 2 < KT) {
            MBARRIER_WAIT_PARITY(sb + SM_FULL(fstage), fphase);
            if (++fstage == STAGES) { fstage = 0; fphase ^= 1; }
        }
    }

    // ---- epilogue ----
    float* outp = out + (size_t)(m_tile * BM) * N_TOTAL + (size_t)n_tile * BN + n_lo;
    const float* biasp = bias + (size_t)n_tile * BN + n_lo;
    #pragma unroll
    for (int mi = 0; mi < 4; mi++) {
        int r0 = m_off + mi * 16 + (lane >> 2);
        #pragma unroll
        for (int nj = 0; nj < NJ; nj++) {
            int c0 = n_off + nj * 8 + (lane & 3) * 2;
            float2 bv = *(const float2*)(biasp + c0);
            float2 v0, v1;
            v0.x = acc[mi][nj][0] + bv.x;
            v0.y = acc[mi][nj][1] + bv.y;
            v1.x = acc[mi][nj][2] + bv.x;
            v1.y = acc[mi][nj][3] + bv.y;
            *(float2*)(outp + (size_t)r0 * N_TOTAL + c0) = v0;
            *(float2*)(outp + (size_t)(r0 + 8) * N_TOTAL + c0) = v1;
        }
    }
}

// ---------------------------------------------------------------------------
// Persistent fused kernel: warps 0-7 GEMM, warp 8 prep.
// ---------------------------------------------------------------------------
__global__ void __launch_bounds__(288, 1) qgl_gemm_kernel(const float* __restrict__ x,
                                                          const int* __restrict__ qw,
                                                          const float* __restrict__ sw,
                                                          const float* __restrict__ bias,
                                                          float* __restrict__ out) {
    extern __shared__ char smem[];
    uint32_t sb = smem_u32(smem);
    int tid = threadIdx.x;
    int lane = tid & 31;
    int wid = tid >> 5;

    int* tileq = (int*)(smem + SM_TILEQ);

    if (tid == 0) {
        #pragma unroll
        for (int s = 0; s < STAGES; s++) {
            MBARRIER_INIT(sb + SM_FULL(s), 1);
            MBARRIER_INIT(sb + SM_EMPTY(s), 8);     // one arrive per GEMM warp
        }
        FENCE_PROXY_ASYNC();
        int t = atomicAdd(&g_tile_ctr, 1);
        tileq[0] = (t < NUNITS) ? t : -1;
    }
    __syncthreads();            // all 9 warps: publish inits + tileq[0]

    if (wid == 8) {
        prep_warp(blockIdx.x, lane, x, qw, sw);
        return;
    }

    int estage = 0, ephase = 1;
    int fstage = 0, fphase = 0;
    int ti = 0;
    int cur = tileq[0];

    // first-unit prologue: wait readiness, fill chunks 0..2
    if (tid == 0 && cur >= 0) {
        wait_unit_ready(cur);
        int mt, nt, nl;
        decode_unit(cur, mt, nt, nl);
        const char* aG = (const char*)d_X16T + (((size_t)mt * KT) << 14);
        const char* bG = (const char*)d_W16T + (((size_t)nt * KT) << 15) + (size_t)nl * 128;
        uint32_t bb = (cur < NFULL) ? 32768u : 8192u;
        #pragma unroll
        for (int s = 0; s < STAGES - 1; s++)
            fill_chunk(sb, s, aG, bG, bb, estage, ephase);
    }

    while (cur >= 0) {
        if (cur < NFULL)
            run_unit<8>(sb, tid, lane, wid, cur, ti, tileq,
                        estage, ephase, fstage, fphase, bias, out);
        else
            run_unit<2>(sb, tid, lane, wid, cur, ti, tileq,
                        estage, ephase, fstage, fphase, bias, out);
        ti++;
        asm volatile("bar.sync 1, 256;" ::: "memory");   // GEMM warps only
        cur = tileq[ti & 3];
    }
}

// ---------------------------------------------------------------------------
extern "C" void kernel_launch(void* const* d_in, const int* in_sizes, int n_in,
                              void* d_out, int out_size) {
    const float* x    = (const float*)d_in[0];
    const int*   qw   = (const int*)d_in[1];
    const float* sw   = (const float*)d_in[2];
    const float* bias = (const float*)d_in[3];
    float* out = (float*)d_out;

    init_kernel<<<1, 1>>>();

    cudaFuncSetAttribute(qgl_gemm_kernel,
                         cudaFuncAttributeMaxDynamicSharedMemorySize, SMEM_TOTAL);
    qgl_gemm_kernel<<<GRID, 288, SMEM_TOTAL>>>(x, qw, sw, bias, out);
}

// round 15
// speedup vs baseline: 2.3687x; 2.3687x over previous
#include <cuda_runtime.h>
#include <cuda_fp16.h>
#include <cstdint>

// ---------------------------------------------------------------------------
// QGroupLinear: y = x @ (qw*sw)^T + bias   (fp32 in/out)
// mma.sync (HMMA) GEMM, fp16 dequant scratch (rel_err ~3e-4).
// R15: champion consolidation = R8 structure + MLP4 prep + lane0 empty-arrive
// + bias register prefetch at unit entry (epilogue becomes store-only).
// ---------------------------------------------------------------------------

#define M_TOTAL 4096
#define N_TOTAL 11008
#define K_TOTAL 4096

#define BM 128
#define BN 256
#define STAGES 4
#define KT (K_TOTAL / 64)           // 64 chunks of 64 halfs
#define TILES_M (M_TOTAL / BM)      // 32
#define TILES_N (N_TOTAL / BN)      // 43
#define NTILES (TILES_M * TILES_N)  // 1376
#define NFULL 1368                  // 152 * 9
#define NUNITS (NFULL + (NTILES - NFULL) * 4)   // 1400
#define GRID 152

#define A_BLK_BYTES (BM * 128)      // 16384
#define B_BLK_BYTES (BN * 128)      // 32768
#define STAGE_BYTES (A_BLK_BYTES + B_BLK_BYTES)   // 49152

#define SM_FULL(s)  ((s) * 8)
#define SM_EMPTY(s) (32 + (s) * 8)
#define SM_TILEQ    64
#define SM_DATA     1024
#define SMEM_TOTAL  (SM_DATA + STAGES * STAGE_BYTES)   // 197632

__device__ uint4 d_X16T[2097152];   // 32 MB : block (m_tile*64+kc) = 16 KB
__device__ uint4 d_W16T[5636096];   // 90 MB : block (n_tile*64+kc) = 32 KB
__device__ int   g_tile_ctr;

// ---------------------------------------------------------------------------
__device__ __forceinline__ uint32_t smem_u32(const void* p) {
    uint32_t a;
    asm("{ .reg .u64 t; cvta.to.shared.u64 t, %1; cvt.u32.u64 %0, t; }"
        : "=r"(a) : "l"(p));
    return a;
}

#define MBARRIER_INIT(addr, cnt) \
    asm volatile("mbarrier.init.shared.b64 [%0], %1;" :: "r"((uint32_t)(addr)), "r"((uint32_t)(cnt)) : "memory")
#define MBARRIER_EXPECT_TX(addr, bytes) \
    asm volatile("mbarrier.arrive.expect_tx.shared.b64 _, [%0], %1;" :: "r"((uint32_t)(addr)), "r"((uint32_t)(bytes)) : "memory")
#define MBARRIER_ARRIVE(addr) \
    asm volatile("mbarrier.arrive.shared.b64 _, [%0];" :: "r"((uint32_t)(addr)) : "memory")
#define FENCE_PROXY_ASYNC() asm volatile("fence.proxy.async.shared::cta;" ::: "memory")

#define MBARRIER_WAIT_PARITY(mbar_smem_addr, phase_parity) do { \
    uint32_t _mbar = (uint32_t)(mbar_smem_addr); \
    uint32_t _parity = (uint32_t)(phase_parity); \
    uint32_t _done; \
    asm volatile( \
        "{\n\t.reg .pred p;\n\t" \
        "mbarrier.try_wait.parity.acquire.cta.shared::cta.b64 p, [%1], %2;\n\t" \
        "selp.b32 %0, 1, 0, p;\n\t}" \
        : "=r"(_done) : "r"(_mbar), "r"(_parity) : "memory"); \
    if (!_done) { \
        asm volatile( \
            "{\n\t.reg .pred P1;\n\t" \
            "WAIT_LOOP_%=:\n\t" \
            "mbarrier.try_wait.parity.acquire.cta.shared::cta.b64 P1, [%0], %1, 0x989680;\n\t" \
            "@P1 bra.uni WAIT_DONE_%=;\n\t" \
            "bra.uni WAIT_LOOP_%=;\n\t" \
            "WAIT_DONE_%=:\n\t}" \
            :: "r"(_mbar), "r"(_parity) : "memory"); \
    } \
} while (0)

#define BULK_G2S(dst, src, bytes, mbar) \
    asm volatile("cp.async.bulk.shared::cta.global.mbarrier::complete_tx::bytes [%0], [%1], %2, [%3];" \
        :: "r"((uint32_t)(dst)), "l"((unsigned long long)(src)), "r"((uint32_t)(bytes)), "r"((uint32_t)(mbar)) : "memory")

__device__ __forceinline__ void ldsm4(uint32_t* r, uint32_t addr) {
    asm volatile("ldmatrix.sync.aligned.m8n8.x4.shared.b16 {%0,%1,%2,%3}, [%4];"
                 : "=r"(r[0]), "=r"(r[1]), "=r"(r[2]), "=r"(r[3]) : "r"(addr));
}

__device__ __forceinline__ void mma16816(float* c, const uint32_t* a,
                                         uint32_t b0, uint32_t b1) {
    asm volatile(
        "mma.sync.aligned.m16n8k16.row.col.f32.f16.f16.f32 "
        "{%0,%1,%2,%3}, {%4,%5,%6,%7}, {%8,%9}, {%0,%1,%2,%3};"
        : "+f"(c[0]), "+f"(c[1]), "+f"(c[2]), "+f"(c[3])
        : "r"(a[0]), "r"(a[1]), "r"(a[2]), "r"(a[3]), "r"(b0), "r"(b1));
}

// unit decode: u < NFULL -> full tile; else quarter slice of tiles 1368..1375
__device__ __forceinline__ void decode_unit(int u, int& mt, int& nt, int& nlo) {
    if (u < NFULL) {
        mt = u & (TILES_M - 1); nt = u >> 5; nlo = 0;
    } else {
        int v = u - NFULL;
        int t = NFULL + (v >> 2);
        mt = t & (TILES_M - 1); nt = t >> 5; nlo = (v & 3) * 64;
    }
}

__device__ __forceinline__ void fill_chunk(uint32_t sb, int cloc,
                                           const char* aG, const char* bG,
                                           uint32_t bbytes,
                                           int& estage, int& ephase) {
    MBARRIER_WAIT_PARITY(sb + SM_EMPTY(estage), ephase);
    if (++estage == STAGES) { estage = 0; ephase ^= 1; }
    int slot = cloc & 3;
    MBARRIER_EXPECT_TX(sb + SM_FULL(slot), A_BLK_BYTES + bbytes);
    BULK_G2S(sb + SM_DATA + slot * STAGE_BYTES,
             __cvta_generic_to_global(aG + ((size_t)cloc << 14)),
             A_BLK_BYTES, sb + SM_FULL(slot));
    BULK_G2S(sb + SM_DATA + slot * STAGE_BYTES + A_BLK_BYTES,
             __cvta_generic_to_global(bG + ((size_t)cloc << 15)),
             bbytes, sb + SM_FULL(slot));
}

// ---------------------------------------------------------------------------
// Fused prep (MLP=4): each thread converts 16 values (4x16B loads in flight).
// ---------------------------------------------------------------------------
#define XB ((M_TOTAL * K_TOTAL / 16) / 256)    // 4096 blocks
#define WB ((N_TOTAL * K_TOTAL / 16) / 256)    // 11008 blocks

__global__ void __launch_bounds__(256) prep_kernel(const float* __restrict__ x,
                                                   const int* __restrict__ qw,
                                                   const float* __restrict__ sw) {
    if (blockIdx.x == 0 && threadIdx.x == 0) g_tile_ctr = 0;
    int b = blockIdx.x;
    if (b < XB) {
        int idx = b * 256 + threadIdx.x;
        int m = idx >> 8;                      // 256 16-half groups per row
        int k0 = (idx & 255) << 4;
        const float4* src = (const float4*)(x + (size_t)m * K_TOTAL + k0);
        float4 v0 = src[0], v1 = src[1], v2 = src[2], v3 = src[3];
        uint4 p0, p1;
        __half2 h;
        h = __floats2half2_rn(v0.x, v0.y); p0.x = *(uint32_t*)&h;
        h = __floats2half2_rn(v0.z, v0.w); p0.y = *(uint32_t*)&h;
        h = __floats2half2_rn(v1.x, v1.y); p0.z = *(uint32_t*)&h;
        h = __floats2half2_rn(v1.z, v1.w); p0.w = *(uint32_t*)&h;
        h = __floats2half2_rn(v2.x, v2.y); p1.x = *(uint32_t*)&h;
        h = __floats2half2_rn(v2.z, v2.w); p1.y = *(uint32_t*)&h;
        h = __floats2half2_rn(v3.x, v3.y); p1.z = *(uint32_t*)&h;
        h = __floats2half2_rn(v3.z, v3.w); p1.w = *(uint32_t*)&h;
        int blk = (m >> 7) * KT + (k0 >> 6);
        int row = m & 127, ch = k0 & 63;
        uint32_t rb = (uint32_t)row * 128;
        uint32_t sw_ = ((uint32_t)(row & 7)) << 4;
        char* base = (char*)d_X16T + ((size_t)blk << 14);
        *(uint4*)(base + rb + (((uint32_t)ch * 2) ^ sw_)) = p0;
        *(uint4*)(base + rb + (((uint32_t)(ch + 8) * 2) ^ sw_)) = p1;
    } else {
        int idx = (b - XB) * 256 + threadIdx.x;
        int n = idx >> 8;
        int k0 = (idx & 255) << 4;
        const int4* src = (const int4*)(qw + (size_t)n * K_TOTAL + k0);
        int4 q0 = src[0], q1 = src[1], q2 = src[2], q3 = src[3];
        float s = sw[n * 32 + (k0 >> 7)];      // 16 values share one group
        uint4 p0, p1;
        __half2 h;
        h = __floats2half2_rn((float)q0.x * s, (float)q0.y * s); p0.x = *(uint32_t*)&h;
        h = __floats2half2_rn((float)q0.z * s, (float)q0.w * s); p0.y = *(uint32_t*)&h;
        h = __floats2half2_rn((float)q1.x * s, (float)q1.y * s); p0.z = *(uint32_t*)&h;
        h = __floats2half2_rn((float)q1.z * s, (float)q1.w * s); p0.w = *(uint32_t*)&h;
        h = __floats2half2_rn((float)q2.x * s, (float)q2.y * s); p1.x = *(uint32_t*)&h;
        h = __floats2half2_rn((float)q2.z * s, (float)q2.w * s); p1.y = *(uint32_t*)&h;
        h = __floats2half2_rn((float)q3.x * s, (float)q3.y * s); p1.z = *(uint32_t*)&h;
        h = __floats2half2_rn((float)q3.z * s, (float)q3.w * s); p1.w = *(uint32_t*)&h;
        int blk = (n >> 8) * KT + (k0 >> 6);
        int row = n & 255, ch = k0 & 63;
        uint32_t rb = (uint32_t)row * 128;
        uint32_t sw_ = ((uint32_t)(row & 7)) << 4;
        char* base = (char*)d_W16T + ((size_t)blk << 15);
        *(uint4*)(base + rb + (((uint32_t)ch * 2) ^ sw_)) = p0;
        *(uint4*)(base + rb + (((uint32_t)(ch + 8) * 2) ^ sw_)) = p1;
    }
}

// ---------------------------------------------------------------------------
// Templated per-unit mainloop. NJ = 8 (full 128x256) or 2 (quarter 128x64).
// Bias prefetched into registers at unit entry; epilogue is store-only.
// ---------------------------------------------------------------------------
template <int NJ>
__device__ __forceinline__ void run_unit(uint32_t sb, int tid, int lane, int wid,
                                         int cur_unit, int ti, int* tileq,
                                         int& estage, int& ephase,
                                         int& fstage, int& fphase,
                                         const float* __restrict__ bias,
                                         float* __restrict__ out) {
    int warp_m = wid & 1;
    int warp_n = wid >> 1;
    int m_off = warp_m * 64;
    int n_off = warp_n * (NJ * 8);

    int m_tile, n_tile, n_lo;
    decode_unit(cur_unit, m_tile, n_tile, n_lo);

    const char* aG = (const char*)d_X16T + (((size_t)m_tile * KT) << 14);
    const char* bG = (const char*)d_W16T + (((size_t)n_tile * KT) << 15) + (size_t)n_lo * 128;
    const uint32_t bbytes = NJ * 4096;

    // bias register prefetch (overlaps the mainloop; epilogue store-only)
    const float* biasp = bias + (size_t)n_tile * BN + n_lo;
    float2 bv[NJ];
    #pragma unroll
    for (int nj = 0; nj < NJ; nj++)
        bv[nj] = *(const float2*)(biasp + n_off + nj * 8 + (lane & 3) * 2);

    int rowA = m_off + (lane & 15);
    uint32_t xorA = (uint32_t)(rowA & 7) << 4;
    uint32_t cbA = ((uint32_t)(lane >> 4)) << 4;
    uint32_t aRow = sb + SM_DATA + (uint32_t)rowA * 128;

    int rowB = n_off + ((lane & 7) | ((lane & 16) >> 1));
    uint32_t xorB = (uint32_t)(rowB & 7) << 4;
    uint32_t cbB = ((uint32_t)((lane >> 3) & 1)) << 4;
    uint32_t bRow = sb + SM_DATA + A_BLK_BYTES + (uint32_t)rowB * 128;

    float acc[4][NJ][4];
    #pragma unroll
    for (int mi = 0; mi < 4; mi++)
        #pragma unroll
        for (int nj = 0; nj < NJ; nj++)
            #pragma unroll
            for (int r = 0; r < 4; r++) acc[mi][nj][r] = 0.0f;

    uint32_t fa[2][4][4], fb[2][NJ / 2][4];

    auto prefetch = [&](int buf, int s, int kk) {
        uint32_t ka = ((uint32_t)kk * 32 + cbA) ^ xorA;
        uint32_t kb = ((uint32_t)kk * 32 + cbB) ^ xorB;
        uint32_t aS = aRow + (uint32_t)s * STAGE_BYTES + ka;
        uint32_t bS = bRow + (uint32_t)s * STAGE_BYTES + kb;
        #pragma unroll
        for (int mi = 0; mi < 4; mi++)
            ldsm4(fa[buf][mi], aS + mi * (16 * 128));
        #pragma unroll
        for (int nj2 = 0; nj2 < NJ / 2; nj2++)
            ldsm4(fb[buf][nj2], bS + nj2 * (16 * 128));
    };

    int next_unit = -1;   // tid0 only

    // unit entry: wait chunks 0,1 and prime fragments
    MBARRIER_WAIT_PARITY(sb + SM_FULL(fstage), fphase);
    if (++fstage == STAGES) { fstage = 0; fphase ^= 1; }
    MBARRIER_WAIT_PARITY(sb + SM_FULL(fstage), fphase);
    if (++fstage == STAGES) { fstage = 0; fphase ^= 1; }
    prefetch(0, 0, 0);

    for (int kt = 0; kt < KT; kt++) {
        // ---- producer (tid0): fill chunk kt+3 (may spill into next unit) ----
        if (tid == 0) {
            if (kt == 0) {
                int t = atomicAdd(&g_tile_ctr, 1);
                next_unit = (t < NUNITS) ? t : -1;
                tileq[(ti + 1) & 3] = next_unit;
            }
            int lt = kt + STAGES - 1;
            if (lt < KT) {
                fill_chunk(sb, lt, aG, bG, bbytes, estage, ephase);
            } else if (next_unit >= 0) {
                int nm, nn, nl;
                decode_unit(next_unit, nm, nn, nl);
                const char* pa = (const char*)d_X16T + (((size_t)nm * KT) << 14);
                const char* pb = (const char*)d_W16T + (((size_t)nn * KT) << 15) + (size_t)nl * 128;
                uint32_t nb = (next_unit < NFULL) ? 32768u : 8192u;
                fill_chunk(sb, lt - KT, pa, pb, nb, estage, ephase);
            }
        }

        int s = kt & (STAGES - 1);
        #pragma unroll
        for (int kk = 0; kk < 4; kk++) {
            int curb = kk & 1, nxt = curb ^ 1;
            if (kk < 3)
                prefetch(nxt, s, kk + 1);
            else if (kt + 1 < KT)
                prefetch(nxt, (kt + 1) & (STAGES - 1), 0);
            // last stage-s read was the kk==2 prefetch: lane0-per-warp arrive
            if (kk == 2 && lane == 0) MBARRIER_ARRIVE(sb + SM_EMPTY(s));
            #pragma unroll
            for (int mi = 0; mi < 4; mi++)
                #pragma unroll
                for (int nj = 0; nj < NJ; nj++)
                    mma16816(acc[mi][nj], fa[curb][mi],
                             fb[curb][nj >> 1][(nj & 1) * 2],
                             fb[curb][nj >> 1][(nj & 1) * 2 + 1]);
        }

        // wait chunk kt+2 (needed at iteration kt+1's kk=3 prefetch)
        if (kt + 2 < KT) {
            MBARRIER_WAIT_PARITY(sb + SM_FULL(fstage), fphase);
            if (++fstage == STAGES) { fstage = 0; fphase ^= 1; }
        }
    }

    // ---- epilogue: store-only (bias already in registers) ----
    float* outp = out + (size_t)(m_tile * BM) * N_TOTAL + (size_t)n_tile * BN + n_lo;
    #pragma unroll
    for (int mi = 0; mi < 4; mi++) {
        int r0 = m_off + mi * 16 + (lane >> 2);
        #pragma unroll
        for (int nj = 0; nj < NJ; nj++) {
            int c0 = n_off + nj * 8 + (lane & 3) * 2;
            float2 v0, v1;
            v0.x = acc[mi][nj][0] + bv[nj].x;
            v0.y = acc[mi][nj][1] + bv[nj].y;
            v1.x = acc[mi][nj][2] + bv[nj].x;
            v1.y = acc[mi][nj][3] + bv[nj].y;
            *(float2*)(outp + (size_t)r0 * N_TOTAL + c0) = v0;
            *(float2*)(outp + (size_t)(r0 + 8) * N_TOTAL + c0) = v1;
        }
    }
}

// ---------------------------------------------------------------------------
// Persistent GEMM driver.
// ---------------------------------------------------------------------------
__global__ void __launch_bounds__(256, 1) qgl_gemm_kernel(const float* __restrict__ bias,
                                                          float* __restrict__ out) {
    extern __shared__ char smem[];
    uint32_t sb = smem_u32(smem);
    int tid = threadIdx.x;
    int lane = tid & 31;
    int wid = tid >> 5;

    int* tileq = (int*)(smem + SM_TILEQ);

    if (tid == 0) {
        #pragma unroll
        for (int s = 0; s < STAGES; s++) {
            MBARRIER_INIT(sb + SM_FULL(s), 1);
            MBARRIER_INIT(sb + SM_EMPTY(s), 8);     // one arrive per warp
        }
        FENCE_PROXY_ASYNC();
        int t = atomicAdd(&g_tile_ctr, 1);
        tileq[0] = (t < NUNITS) ? t : -1;
    }
    __syncthreads();

    int estage = 0, ephase = 1;
    int fstage = 0, fphase = 0;
    int ti = 0;
    int cur = tileq[0];

    // first-unit prologue: fill chunks 0..2
    if (tid == 0 && cur >= 0) {
        int mt, nt, nl;
        decode_unit(cur, mt, nt, nl);
        const char* aG = (const char*)d_X16T + (((size_t)mt * KT) << 14);
        const char* bG = (const char*)d_W16T + (((size_t)nt * KT) << 15) + (size_t)nl * 128;
        uint32_t bb = (cur < NFULL) ? 32768u : 8192u;
        #pragma unroll
        for (int s = 0; s < STAGES - 1; s++)
            fill_chunk(sb, s, aG, bG, bb, estage, ephase);
    }

    while (cur >= 0) {
        if (cur < NFULL)
            run_unit<8>(sb, tid, lane, wid, cur, ti, tileq,
                        estage, ephase, fstage, fphase, bias, out);
        else
            run_unit<2>(sb, tid, lane, wid, cur, ti, tileq,
                        estage, ephase, fstage, fphase, bias, out);
        ti++;
        __syncthreads();
        cur = tileq[ti & 3];
    }
}

// ---------------------------------------------------------------------------
extern "C" void kernel_launch(void* const* d_in, const int* in_sizes, int n_in,
                              void* d_out, int out_size) {
    const float* x    = (const float*)d_in[0];
    const int*   qw   = (const int*)d_in[1];
    const float* sw   = (const float*)d_in[2];
    const float* bias = (const float*)d_in[3];
    float* out = (float*)d_out;

    prep_kernel<<<XB + WB, 256>>>(x, qw, sw);

    cudaFuncSetAttribute(qgl_gemm_kernel,
                         cudaFuncAttributeMaxDynamicSharedMemorySize, SMEM_TOTAL);
    qgl_gemm_kernel<<<TILES_M * TILES_N, 256, SMEM_TOTAL>>>(bias, out);
}

// round 16
// speedup vs baseline: 2.3766x; 1.0033x over previous
#include <cuda_runtime.h>
#include <cuda_fp16.h>
#include <cstdint>

// ---------------------------------------------------------------------------
// QGroupLinear: y = x @ (qw*sw)^T + bias   (fp32 in/out)
// mma.sync (HMMA) GEMM, fp16 dequant scratch (rel_err ~3e-4).
// R16: R15 champion + K-split tail. 1368 full tiles = 9 exact waves; the 8
// leftover tiles are split 16-way along K (4 chunks per unit, 128 units =
// one short wave). K-split units accumulate via red.global.add.f32 into
// bias-pre-seeded output rows (seeded by prep).
// ---------------------------------------------------------------------------

#define M_TOTAL 4096
#define N_TOTAL 11008
#define K_TOTAL 4096

#define BM 128
#define BN 256
#define STAGES 4
#define KT (K_TOTAL / 64)           // 64 chunks of 64 halfs
#define TILES_M (M_TOTAL / BM)      // 32
#define TILES_N (N_TOTAL / BN)      // 43
#define NTILES (TILES_M * TILES_N)  // 1376
#define NFULL 1368                  // 152 * 9 (exact waves)
#define KSPLIT 16                   // leftover tiles split 16-way along K
#define KTU_TAIL (KT / KSPLIT)      // 4 chunks per tail unit
#define NUNITS (NFULL + (NTILES - NFULL) * KSPLIT)   // 1496
#define GRID 152

#define A_BLK_BYTES (BM * 128)      // 16384
#define B_BLK_BYTES (BN * 128)      // 32768
#define STAGE_BYTES (A_BLK_BYTES + B_BLK_BYTES)   // 49152

#define SM_FULL(s)  ((s) * 8)
#define SM_EMPTY(s) (32 + (s) * 8)
#define SM_TILEQ    64
#define SM_DATA     1024
#define SMEM_TOTAL  (SM_DATA + STAGES * STAGE_BYTES)   // 197632

__device__ uint4 d_X16T[2097152];   // 32 MB : block (m_tile*64+kc) = 16 KB
__device__ uint4 d_W16T[5636096];   // 90 MB : block (n_tile*64+kc) = 32 KB
__device__ int   g_tile_ctr;

// ---------------------------------------------------------------------------
__device__ __forceinline__ uint32_t smem_u32(const void* p) {
    uint32_t a;
    asm("{ .reg .u64 t; cvta.to.shared.u64 t, %1; cvt.u32.u64 %0, t; }"
        : "=r"(a) : "l"(p));
    return a;
}

#define MBARRIER_INIT(addr, cnt) \
    asm volatile("mbarrier.init.shared.b64 [%0], %1;" :: "r"((uint32_t)(addr)), "r"((uint32_t)(cnt)) : "memory")
#define MBARRIER_EXPECT_TX(addr, bytes) \
    asm volatile("mbarrier.arrive.expect_tx.shared.b64 _, [%0], %1;" :: "r"((uint32_t)(addr)), "r"((uint32_t)(bytes)) : "memory")
#define MBARRIER_ARRIVE(addr) \
    asm volatile("mbarrier.arrive.shared.b64 _, [%0];" :: "r"((uint32_t)(addr)) : "memory")
#define FENCE_PROXY_ASYNC() asm volatile("fence.proxy.async.shared::cta;" ::: "memory")

#define MBARRIER_WAIT_PARITY(mbar_smem_addr, phase_parity) do { \
    uint32_t _mbar = (uint32_t)(mbar_smem_addr); \
    uint32_t _parity = (uint32_t)(phase_parity); \
    uint32_t _done; \
    asm volatile( \
        "{\n\t.reg .pred p;\n\t" \
        "mbarrier.try_wait.parity.acquire.cta.shared::cta.b64 p, [%1], %2;\n\t" \
        "selp.b32 %0, 1, 0, p;\n\t}" \
        : "=r"(_done) : "r"(_mbar), "r"(_parity) : "memory"); \
    if (!_done) { \
        asm volatile( \
            "{\n\t.reg .pred P1;\n\t" \
            "WAIT_LOOP_%=:\n\t" \
            "mbarrier.try_wait.parity.acquire.cta.shared::cta.b64 P1, [%0], %1, 0x989680;\n\t" \
            "@P1 bra.uni WAIT_DONE_%=;\n\t" \
            "bra.uni WAIT_LOOP_%=;\n\t" \
            "WAIT_DONE_%=:\n\t}" \
            :: "r"(_mbar), "r"(_parity) : "memory"); \
    } \
} while (0)

#define BULK_G2S(dst, src, bytes, mbar) \
    asm volatile("cp.async.bulk.shared::cta.global.mbarrier::complete_tx::bytes [%0], [%1], %2, [%3];" \
        :: "r"((uint32_t)(dst)), "l"((unsigned long long)(src)), "r"((uint32_t)(bytes)), "r"((uint32_t)(mbar)) : "memory")

__device__ __forceinline__ void ldsm4(uint32_t* r, uint32_t addr) {
    asm volatile("ldmatrix.sync.aligned.m8n8.x4.shared.b16 {%0,%1,%2,%3}, [%4];"
                 : "=r"(r[0]), "=r"(r[1]), "=r"(r[2]), "=r"(r[3]) : "r"(addr));
}

__device__ __forceinline__ void mma16816(float* c, const uint32_t* a,
                                         uint32_t b0, uint32_t b1) {
    asm volatile(
        "mma.sync.aligned.m16n8k16.row.col.f32.f16.f16.f32 "
        "{%0,%1,%2,%3}, {%4,%5,%6,%7}, {%8,%9}, {%0,%1,%2,%3};"
        : "+f"(c[0]), "+f"(c[1]), "+f"(c[2]), "+f"(c[3])
        : "r"(a[0]), "r"(a[1]), "r"(a[2]), "r"(a[3]), "r"(b0), "r"(b1));
}

__device__ __forceinline__ void red_f32(float* p, float v) {
    asm volatile("red.global.add.f32 [%0], %1;"
                 :: "l"(__cvta_generic_to_global(p)), "f"(v) : "memory");
}

// unit decode. u < NFULL: full tile (64 chunks). Else: K-split unit of tiles
// 1368..1375: v = u-NFULL, tile = NFULL + (v>>4), kbase = (v&15)*KTU_TAIL.
__device__ __forceinline__ void decode_unit(int u, int& mt, int& nt, int& kbase) {
    if (u < NFULL) {
        mt = u & (TILES_M - 1); nt = u >> 5; kbase = 0;
    } else {
        int v = u - NFULL;
        int t = NFULL + (v >> 4);
        mt = t & (TILES_M - 1); nt = t >> 5;
        kbase = (v & (KSPLIT - 1)) * KTU_TAIL;
    }
}

// chunk-base-adjusted source pointers for a unit (A/B chunks are uniform size)
__device__ __forceinline__ void unit_srcs(int u, const char*& aGu, const char*& bGu) {
    int mt, nt, kb;
    decode_unit(u, mt, nt, kb);
    aGu = (const char*)d_X16T + (((size_t)mt * KT + kb) << 14);
    bGu = (const char*)d_W16T + (((size_t)nt * KT + kb) << 15);
}

__device__ __forceinline__ void fill_chunk(uint32_t sb, int cloc,
                                           const char* aG, const char* bG,
                                           int& estage, int& ephase) {
    MBARRIER_WAIT_PARITY(sb + SM_EMPTY(estage), ephase);
    if (++estage == STAGES) { estage = 0; ephase ^= 1; }
    int slot = cloc & 3;
    MBARRIER_EXPECT_TX(sb + SM_FULL(slot), STAGE_BYTES);
    BULK_G2S(sb + SM_DATA + slot * STAGE_BYTES,
             __cvta_generic_to_global(aG + ((size_t)cloc << 14)),
             A_BLK_BYTES, sb + SM_FULL(slot));
    BULK_G2S(sb + SM_DATA + slot * STAGE_BYTES + A_BLK_BYTES,
             __cvta_generic_to_global(bG + ((size_t)cloc << 15)),
             B_BLK_BYTES, sb + SM_FULL(slot));
}

// ---------------------------------------------------------------------------
// Fused prep (MLP=4) + bias seeding of the 8 K-split tiles' output regions.
// ---------------------------------------------------------------------------
#define XB ((M_TOTAL * K_TOTAL / 16) / 256)    // 4096 blocks
#define WB ((N_TOTAL * K_TOTAL / 16) / 256)    // 11008 blocks
#define SB ((NTILES - NFULL) * (BM * BN) / (256 * 4))   // 256 seed blocks

__global__ void __launch_bounds__(256) prep_kernel(const float* __restrict__ x,
                                                   const int* __restrict__ qw,
                                                   const float* __restrict__ sw,
                                                   const float* __restrict__ bias,
                                                   float* __restrict__ out) {
    if (blockIdx.x == 0 && threadIdx.x == 0) g_tile_ctr = 0;
    int b = blockIdx.x;
    if (b < XB) {
        int idx = b * 256 + threadIdx.x;
        int m = idx >> 8;                      // 256 16-half groups per row
        int k0 = (idx & 255) << 4;
        const float4* src = (const float4*)(x + (size_t)m * K_TOTAL + k0);
        float4 v0 = src[0], v1 = src[1], v2 = src[2], v3 = src[3];
        uint4 p0, p1;
        __half2 h;
        h = __floats2half2_rn(v0.x, v0.y); p0.x = *(uint32_t*)&h;
        h = __floats2half2_rn(v0.z, v0.w); p0.y = *(uint32_t*)&h;
        h = __floats2half2_rn(v1.x, v1.y); p0.z = *(uint32_t*)&h;
        h = __floats2half2_rn(v1.z, v1.w); p0.w = *(uint32_t*)&h;
        h = __floats2half2_rn(v2.x, v2.y); p1.x = *(uint32_t*)&h;
        h = __floats2half2_rn(v2.z, v2.w); p1.y = *(uint32_t*)&h;
        h = __floats2half2_rn(v3.x, v3.y); p1.z = *(uint32_t*)&h;
        h = __floats2half2_rn(v3.z, v3.w); p1.w = *(uint32_t*)&h;
        int blk = (m >> 7) * KT + (k0 >> 6);
        int row = m & 127, ch = k0 & 63;
        uint32_t rb = (uint32_t)row * 128;
        uint32_t sw_ = ((uint32_t)(row & 7)) << 4;
        char* base = (char*)d_X16T + ((size_t)blk << 14);
        *(uint4*)(base + rb + (((uint32_t)ch * 2) ^ sw_)) = p0;
        *(uint4*)(base + rb + (((uint32_t)(ch + 8) * 2) ^ sw_)) = p1;
    } else if (b < XB + WB) {
        int idx = (b - XB) * 256 + threadIdx.x;
        int n = idx >> 8;
        int k0 = (idx & 255) << 4;
        const int4* src = (const int4*)(qw + (size_t)n * K_TOTAL + k0);
        int4 q0 = src[0], q1 = src[1], q2 = src[2], q3 = src[3];
        float s = sw[n * 32 + (k0 >> 7)];      // 16 values share one group
        uint4 p0, p1;
        __half2 h;
        h = __floats2half2_rn((float)q0.x * s, (float)q0.y * s); p0.x = *(uint32_t*)&h;
        h = __floats2half2_rn((float)q0.z * s, (float)q0.w * s); p0.y = *(uint32_t*)&h;
        h = __floats2half2_rn((float)q1.x * s, (float)q1.y * s); p0.z = *(uint32_t*)&h;
        h = __floats2half2_rn((float)q1.z * s, (float)q1.w * s); p0.w = *(uint32_t*)&h;
        h = __floats2half2_rn((float)q2.x * s, (float)q2.y * s); p1.x = *(uint32_t*)&h;
        h = __floats2half2_rn((float)q2.z * s, (float)q2.w * s); p1.y = *(uint32_t*)&h;
        h = __floats2half2_rn((float)q3.x * s, (float)q3.y * s); p1.z = *(uint32_t*)&h;
        h = __floats2half2_rn((float)q3.z * s, (float)q3.w * s); p1.w = *(uint32_t*)&h;
        int blk = (n >> 8) * KT + (k0 >> 6);
        int row = n & 255, ch = k0 & 63;
        uint32_t rb = (uint32_t)row * 128;
        uint32_t sw_ = ((uint32_t)(row & 7)) << 4;
        char* base = (char*)d_W16T + ((size_t)blk << 15);
        *(uint4*)(base + rb + (((uint32_t)ch * 2) ^ sw_)) = p0;
        *(uint4*)(base + rb + (((uint32_t)(ch + 8) * 2) ^ sw_)) = p1;
    } else {
        // seed K-split tiles' out regions with bias (red-add accumulates on top)
        int b3 = b - XB - WB;                  // 0..255, 32 blocks per tile
        int t = NFULL + (b3 >> 5);             // tile 1368..1375
        int mt = t & (TILES_M - 1), nt = t >> 5;
        int e = ((b3 & 31) * 256 + threadIdx.x) * 4;   // element in tile
        int row = e >> 8, col = e & 255;
        const float4 bv = *(const float4*)(bias + (size_t)nt * BN + col);
        *(float4*)(out + (size_t)(mt * BM + row) * N_TOTAL + (size_t)nt * BN + col) = bv;
    }
}

// ---------------------------------------------------------------------------
// Per-unit mainloop. KS=false: full tile, kt_u=64, store+bias epilogue.
// KS=true: K-split unit, kt_u=4, red.global.add epilogue (bias pre-seeded).
// ---------------------------------------------------------------------------
template <bool KS>
__device__ __forceinline__ void run_unit(uint32_t sb, int tid, int lane, int wid,
                                         int cur_unit, int kt_u, int ti, int* tileq,
                                         int& estage, int& ephase,
                                         int& fstage, int& fphase,
                                         const float* __restrict__ bias,
                                         float* __restrict__ out) {
    int warp_m = wid & 1;
    int warp_n = wid >> 1;
    int m_off = warp_m * 64;
    int n_off = warp_n * 64;

    int m_tile, n_tile, kbase;
    decode_unit(cur_unit, m_tile, n_tile, kbase);

    const char* aG = (const char*)d_X16T + (((size_t)m_tile * KT + kbase) << 14);
    const char* bG = (const char*)d_W16T + (((size_t)n_tile * KT + kbase) << 15);

    // bias register prefetch (full tiles only; K-split tiles are pre-seeded)
    float2 bv[8];
    if (!KS) {
        const float* biasp = bias + (size_t)n_tile * BN;
        #pragma unroll
        for (int nj = 0; nj < 8; nj++)
            bv[nj] = *(const float2*)(biasp + n_off + nj * 8 + (lane & 3) * 2);
    }

    int rowA = m_off + (lane & 15);
    uint32_t xorA = (uint32_t)(rowA & 7) << 4;
    uint32_t cbA = ((uint32_t)(lane >> 4)) << 4;
    uint32_t aRow = sb + SM_DATA + (uint32_t)rowA * 128;

    int rowB = n_off + ((lane & 7) | ((lane & 16) >> 1));
    uint32_t xorB = (uint32_t)(rowB & 7) << 4;
    uint32_t cbB = ((uint32_t)((lane >> 3) & 1)) << 4;
    uint32_t bRow = sb + SM_DATA + A_BLK_BYTES + (uint32_t)rowB * 128;

    float acc[4][8][4];
    #pragma unroll
    for (int mi = 0; mi < 4; mi++)
        #pragma unroll
        for (int nj = 0; nj < 8; nj++)
            #pragma unroll
            for (int r = 0; r < 4; r++) acc[mi][nj][r] = 0.0f;

    uint32_t fa[2][4][4], fb[2][4][4];

    auto prefetch = [&](int buf, int s, int kk) {
        uint32_t ka = ((uint32_t)kk * 32 + cbA) ^ xorA;
        uint32_t kb = ((uint32_t)kk * 32 + cbB) ^ xorB;
        uint32_t aS = aRow + (uint32_t)s * STAGE_BYTES + ka;
        uint32_t bS = bRow + (uint32_t)s * STAGE_BYTES + kb;
        #pragma unroll
        for (int mi = 0; mi < 4; mi++)
            ldsm4(fa[buf][mi], aS + mi * (16 * 128));
        #pragma unroll
        for (int nj2 = 0; nj2 < 4; nj2++)
            ldsm4(fb[buf][nj2], bS + nj2 * (16 * 128));
    };

    int next_unit = -1;   // tid0 only

    // unit entry: wait chunks 0,1 and prime fragments
    MBARRIER_WAIT_PARITY(sb + SM_FULL(fstage), fphase);
    if (++fstage == STAGES) { fstage = 0; fphase ^= 1; }
    MBARRIER_WAIT_PARITY(sb + SM_FULL(fstage), fphase);
    if (++fstage == STAGES) { fstage = 0; fphase ^= 1; }
    prefetch(0, 0, 0);

    for (int kt = 0; kt < kt_u; kt++) {
        // ---- producer (tid0): fill chunk kt+3 (may spill into next unit) ----
        if (tid == 0) {
            if (kt == 0) {
                int t = atomicAdd(&g_tile_ctr, 1);
                next_unit = (t < NUNITS) ? t : -1;
                tileq[(ti + 1) & 3] = next_unit;
            }
            int lt = kt + STAGES - 1;
            if (lt < kt_u) {
                fill_chunk(sb, lt, aG, bG, estage, ephase);
            } else if (next_unit >= 0) {
                const char *pa, *pb;
                unit_srcs(next_unit, pa, pb);
                fill_chunk(sb, lt - kt_u, pa, pb, estage, ephase);
            }
        }

        int s = kt & (STAGES - 1);
        #pragma unroll
        for (int kk = 0; kk < 4; kk++) {
            int curb = kk & 1, nxt = curb ^ 1;
            if (kk < 3)
                prefetch(nxt, s, kk + 1);
            else if (kt + 1 < kt_u)
                prefetch(nxt, (kt + 1) & (STAGES - 1), 0);
            // last stage-s read was the kk==2 prefetch: lane0-per-warp arrive
            if (kk == 2 && lane == 0) MBARRIER_ARRIVE(sb + SM_EMPTY(s));
            #pragma unroll
            for (int mi = 0; mi < 4; mi++)
                #pragma unroll
                for (int nj = 0; nj < 8; nj++)
                    mma16816(acc[mi][nj], fa[curb][mi],
                             fb[curb][nj >> 1][(nj & 1) * 2],
                             fb[curb][nj >> 1][(nj & 1) * 2 + 1]);
        }

        // wait chunk kt+2 (needed at iteration kt+1's kk=3 prefetch)
        if (kt + 2 < kt_u) {
            MBARRIER_WAIT_PARITY(sb + SM_FULL(fstage), fphase);
            if (++fstage == STAGES) { fstage = 0; fphase ^= 1; }
        }
    }

    // ---- epilogue ----
    float* outp = out + (size_t)(m_tile * BM) * N_TOTAL + (size_t)n_tile * BN;
    #pragma unroll
    for (int mi = 0; mi < 4; mi++) {
        int r0 = m_off + mi * 16 + (lane >> 2);
        #pragma unroll
        for (int nj = 0; nj < 8; nj++) {
            int c0 = n_off + nj * 8 + (lane & 3) * 2;
            if (KS) {
                float* p0 = outp + (size_t)r0 * N_TOTAL + c0;
                float* p1 = outp + (size_t)(r0 + 8) * N_TOTAL + c0;
                red_f32(p0, acc[mi][nj][0]);
                red_f32(p0 + 1, acc[mi][nj][1]);
                red_f32(p1, acc[mi][nj][2]);
                red_f32(p1 + 1, acc[mi][nj][3]);
            } else {
                float2 v0, v1;
                v0.x = acc[mi][nj][0] + bv[nj].x;
                v0.y = acc[mi][nj][1] + bv[nj].y;
                v1.x = acc[mi][nj][2] + bv[nj].x;
                v1.y = acc[mi][nj][3] + bv[nj].y;
                *(float2*)(outp + (size_t)r0 * N_TOTAL + c0) = v0;
                *(float2*)(outp + (size_t)(r0 + 8) * N_TOTAL + c0) = v1;
            }
        }
    }
}

// ---------------------------------------------------------------------------
// Persistent GEMM driver.
// ---------------------------------------------------------------------------
__global__ void __launch_bounds__(256, 1) qgl_gemm_kernel(const float* __restrict__ bias,
                                                          float* __restrict__ out) {
    extern __shared__ char smem[];
    uint32_t sb = smem_u32(smem);
    int tid = threadIdx.x;
    int lane = tid & 31;
    int wid = tid >> 5;

    int* tileq = (int*)(smem + SM_TILEQ);

    if (tid == 0) {
        #pragma unroll
        for (int s = 0; s < STAGES; s++) {
            MBARRIER_INIT(sb + SM_FULL(s), 1);
            MBARRIER_INIT(sb + SM_EMPTY(s), 8);     // one arrive per warp
        }
        FENCE_PROXY_ASYNC();
        int t = atomicAdd(&g_tile_ctr, 1);
        tileq[0] = (t < NUNITS) ? t : -1;
    }
    __syncthreads();

    int estage = 0, ephase = 1;
    int fstage = 0, fphase = 0;
    int ti = 0;
    int cur = tileq[0];

    // first-unit prologue: fill chunks 0..2
    if (tid == 0 && cur >= 0) {
        const char *aG, *bG;
        unit_srcs(cur, aG, bG);
        #pragma unroll
        for (int s = 0; s < STAGES - 1; s++)
            fill_chunk(sb, s, aG, bG, estage, ephase);
    }

    while (cur >= 0) {
        if (cur < NFULL)
            run_unit<false>(sb, tid, lane, wid, cur, KT, ti, tileq,
                            estage, ephase, fstage, fphase, bias, out);
        else
            run_unit<true>(sb, tid, lane, wid, cur, KTU_TAIL, ti, tileq,
                           estage, ephase, fstage, fphase, bias, out);
        ti++;
        __syncthreads();
        cur = tileq[ti & 3];
    }
}

// ---------------------------------------------------------------------------
extern "C" void kernel_launch(void* const* d_in, const int* in_sizes, int n_in,
                              void* d_out, int out_size) {
    const float* x    = (const float*)d_in[0];
    const int*   qw   = (const int*)d_in[1];
    const float* sw   = (const float*)d_in[2];
    const float* bias = (const float*)d_in[3];
    float* out = (float*)d_out;

    prep_kernel<<<XB + WB + SB, 256>>>(x, qw, sw, bias, out);

    cudaFuncSetAttribute(qgl_gemm_kernel,
                         cudaFuncAttributeMaxDynamicSharedMemorySize, SMEM_TOTAL);
    qgl_gemm_kernel<<<GRID, 256, SMEM_TOTAL>>>(bias, out);
}